// round 3
// baseline (speedup 1.0000x reference)
#include <cuda_runtime.h>
#include <math.h>

#define TT 512
#define BB 32
#define HH 512
#define NROWS 16384
#define LDK 528
#define NG 4096

__device__ float g_xp  [(size_t)NROWS * LDK];
__device__ float g_wp  [(size_t)NG * LDK];
__device__ float g_bias[NG];
__device__ float g_pre [(size_t)NROWS * NG];
__device__ float g_hseq[(size_t)2 * NROWS * HH];
__device__ float g_em  [(size_t)NROWS * 6];
__device__ int   g_bars[4];

// ---- K1: x = [emb[ids] | eeg[:,:,4:6] | pad] as [t*32+b][528] --------------
__global__ void build_x_k(const int* __restrict__ ids, const float* __restrict__ eeg,
                          const float* __restrict__ emb) {
    int row = blockIdx.x, t = row >> 5, b = row & 31;
    int id = ids[b * TT + t];
    const float* er = emb + (size_t)id * 512;
    float* xr = g_xp + (size_t)row * LDK;
    for (int d = threadIdx.x; d < LDK; d += blockDim.x) {
        float v;
        if (d < 512)      v = er[d];
        else if (d < 514) v = eeg[((size_t)(b * TT + t)) * 8 + 4 + (d - 512)];
        else              v = 0.f;
        xr[d] = v;
    }
}

// ---- K1b: pack W_ih both dirs to [4096][528], bias, reset barriers ---------
__global__ void pack_w_k(const float* __restrict__ wf, const float* __restrict__ wb,
                         const float* __restrict__ bf, const float* __restrict__ bbv) {
    int r = blockIdx.x;
    if (r == 0 && threadIdx.x < 4) g_bars[threadIdx.x] = 0;
    const float* src = (r < 2048) ? (wf + (size_t)r * 514) : (wb + (size_t)(r - 2048) * 514);
    float* dst = g_wp + (size_t)r * LDK;
    for (int d = threadIdx.x; d < LDK; d += blockDim.x)
        dst[d] = (d < 514) ? src[d] : 0.f;
    if (threadIdx.x == 0) g_bias[r] = (r < 2048) ? bf[r] : bbv[r - 2048];
}

// ---- K2: pre = x @ Wp^T + bias, M=16384 N=4096 K=528 -----------------------
__global__ void __launch_bounds__(256) gemm_pre_k() {
    __shared__ __align__(16) float As[16][64];
    __shared__ __align__(16) float Bs[16][64];
    const int bn = blockIdx.x * 64, bm = blockIdx.y * 64;
    const int tid = threadIdx.x;
    const int tx = tid & 15, ty = tid >> 4;
    const int lr = tid >> 2, lc = (tid & 3) << 2;
    float acc[4][4];
#pragma unroll
    for (int i = 0; i < 4; i++)
#pragma unroll
        for (int j = 0; j < 4; j++) acc[i][j] = 0.f;
    const float* Ap = g_xp + (size_t)(bm + lr) * LDK + lc;
    const float* Wp = g_wp + (size_t)(bn + lr) * LDK + lc;
    for (int k0 = 0; k0 < LDK; k0 += 16) {
        float4 av = *(const float4*)(Ap + k0);
        float4 bv = *(const float4*)(Wp + k0);
        As[lc+0][lr]=av.x; As[lc+1][lr]=av.y; As[lc+2][lr]=av.z; As[lc+3][lr]=av.w;
        Bs[lc+0][lr]=bv.x; Bs[lc+1][lr]=bv.y; Bs[lc+2][lr]=bv.z; Bs[lc+3][lr]=bv.w;
        __syncthreads();
#pragma unroll
        for (int k = 0; k < 16; k++) {
            float4 ra = *(const float4*)&As[k][ty << 2];
            float4 rb = *(const float4*)&Bs[k][tx << 2];
            acc[0][0]=fmaf(ra.x,rb.x,acc[0][0]); acc[0][1]=fmaf(ra.x,rb.y,acc[0][1]);
            acc[0][2]=fmaf(ra.x,rb.z,acc[0][2]); acc[0][3]=fmaf(ra.x,rb.w,acc[0][3]);
            acc[1][0]=fmaf(ra.y,rb.x,acc[1][0]); acc[1][1]=fmaf(ra.y,rb.y,acc[1][1]);
            acc[1][2]=fmaf(ra.y,rb.z,acc[1][2]); acc[1][3]=fmaf(ra.y,rb.w,acc[1][3]);
            acc[2][0]=fmaf(ra.z,rb.x,acc[2][0]); acc[2][1]=fmaf(ra.z,rb.y,acc[2][1]);
            acc[2][2]=fmaf(ra.z,rb.z,acc[2][2]); acc[2][3]=fmaf(ra.z,rb.w,acc[2][3]);
            acc[3][0]=fmaf(ra.w,rb.x,acc[3][0]); acc[3][1]=fmaf(ra.w,rb.y,acc[3][1]);
            acc[3][2]=fmaf(ra.w,rb.z,acc[3][2]); acc[3][3]=fmaf(ra.w,rb.w,acc[3][3]);
        }
        __syncthreads();
    }
    const int cn = bn + (tx << 2);
    float4 bvec = *(const float4*)&g_bias[cn];
#pragma unroll
    for (int i = 0; i < 4; i++) {
        float4 o;
        o.x=acc[i][0]+bvec.x; o.y=acc[i][1]+bvec.y; o.z=acc[i][2]+bvec.z; o.w=acc[i][3]+bvec.w;
        *(float4*)(g_pre + (size_t)(bm + (ty << 2) + i) * NG + cn) = o;
    }
}

// ---- K3: persistent BiLSTM recurrence. 128 CTAs = dir(2)*hchunk(32)*bhalf(2)
__global__ void __launch_bounds__(256, 1) lstm_rec_k(const float* __restrict__ whhf,
                                                     const float* __restrict__ whhb) {
    extern __shared__ float smem[];
    float4* WT4 = (float4*)smem;          // [k4=128][row=64]  128 KB
    float*  hs  = smem + 32768;           // [16][512]          32 KB
    float*  gsm = smem + 40960;           // [64][17]
    const int tid = threadIdx.x, cta = blockIdx.x;
    const int dir = cta >> 6, sub = cta & 63;
    const int hchunk = sub >> 1, bhalf = sub & 1;
    const int grp = dir * 2 + bhalf;
    const int j0 = hchunk * 16, b0 = bhalf * 16;
    const float* W = dir ? whhb : whhf;
    for (int idx = tid; idx < 8192; idx += 256) {
        int r = idx & 63, k4 = idx >> 6;
        int gate = r >> 4, jl = r & 15;
        WT4[idx] = *(const float4*)(W + (size_t)(gate * 512 + j0 + jl) * 512 + k4 * 4);
    }
    const int ra = tid & 31, bbt = tid >> 5;     // dot phase
    const int gj = tid & 15, gb = tid >> 4;      // gate phase
    const int bglob = b0 + gb;
    float c_state = 0.f;
    const float4* hs4 = (const float4*)hs;
    __syncthreads();

    for (int step = 0; step < TT; step++) {
        const int t = dir ? (TT - 1 - step) : step;
        const int tp = dir ? (t + 1) : (t - 1);
        if (step > 0) {
            if (tid == 0) {
                const int target = 32 * step;
                while (atomicAdd(&g_bars[grp], 0) < target) __nanosleep(64);
            }
            __syncthreads();
            const float4* hp = (const float4*)(g_hseq + (((size_t)dir * TT + tp) * BB + b0) * HH);
            for (int i = tid; i < 2048; i += 256)
                ((float4*)hs)[i] = __ldcg(hp + i);
        }
        __syncthreads();

        float a00=0.f, a01=0.f, a10=0.f, a11=0.f;
        if (step > 0) {
#pragma unroll 4
            for (int k4 = 0; k4 < 128; k4++) {
                float4 w0 = WT4[k4 * 64 + ra];
                float4 w1 = WT4[k4 * 64 + ra + 32];
                float4 h0 = hs4[bbt * 128 + k4];
                float4 h1 = hs4[(bbt + 8) * 128 + k4];
                a00=fmaf(w0.x,h0.x,a00); a00=fmaf(w0.y,h0.y,a00); a00=fmaf(w0.z,h0.z,a00); a00=fmaf(w0.w,h0.w,a00);
                a01=fmaf(w0.x,h1.x,a01); a01=fmaf(w0.y,h1.y,a01); a01=fmaf(w0.z,h1.z,a01); a01=fmaf(w0.w,h1.w,a01);
                a10=fmaf(w1.x,h0.x,a10); a10=fmaf(w1.y,h0.y,a10); a10=fmaf(w1.z,h0.z,a10); a10=fmaf(w1.w,h0.w,a10);
                a11=fmaf(w1.x,h1.x,a11); a11=fmaf(w1.y,h1.y,a11); a11=fmaf(w1.z,h1.z,a11); a11=fmaf(w1.w,h1.w,a11);
            }
        }
        gsm[ra*17+bbt]=a00; gsm[ra*17+bbt+8]=a01;
        gsm[(ra+32)*17+bbt]=a10; gsm[(ra+32)*17+bbt+8]=a11;
        __syncthreads();

        const float* prow = g_pre + ((size_t)t * BB + bglob) * NG + dir * 2048 + j0 + gj;
        float gi = gsm[(gj     )*17+gb] + prow[0];
        float gf = gsm[(16 + gj)*17+gb] + prow[512];
        float gg = gsm[(32 + gj)*17+gb] + prow[1024];
        float go = gsm[(48 + gj)*17+gb] + prow[1536];
        float si = 1.f/(1.f+expf(-gi));
        float sf = 1.f/(1.f+expf(-gf));
        float so = 1.f/(1.f+expf(-go));
        c_state = sf * c_state + si * tanhf(gg);
        float h = so * tanhf(c_state);
        g_hseq[(((size_t)dir * TT + t) * BB + bglob) * HH + j0 + gj] = h;
        __threadfence();
        __syncthreads();
        if (tid == 0) atomicAdd(&g_bars[grp], 1);
    }
}

// ---- K4: LayerNorm(1024) + ReLU + emission (K=6) ---------------------------
__global__ void __launch_bounds__(256) ln_emit_k(const float* __restrict__ lng,
                                                 const float* __restrict__ lnb,
                                                 const float* __restrict__ wout,
                                                 const float* __restrict__ bout) {
    __shared__ float sh[1024];
    __shared__ float rs[8], rs2[8];
    __shared__ float s_mu, s_rstd;
    const int row = blockIdx.x, tid = threadIdx.x;
    const int lane = tid & 31, w = tid >> 5;
    const float* hf = g_hseq + (size_t)row * 512;
    const float* hb = g_hseq + (size_t)(NROWS + row) * 512;
    float s = 0.f, s2 = 0.f;
#pragma unroll
    for (int i = 0; i < 4; i++) {
        int idx = tid + i * 256;
        float x = (idx < 512) ? hf[idx] : hb[idx - 512];
        sh[idx] = x; s += x; s2 += x * x;
    }
    for (int o = 16; o; o >>= 1) {
        s  += __shfl_down_sync(0xffffffffu, s, o);
        s2 += __shfl_down_sync(0xffffffffu, s2, o);
    }
    if (!lane) { rs[w] = s; rs2[w] = s2; }
    __syncthreads();
    if (!tid) {
        float S = 0.f, S2 = 0.f;
        for (int i = 0; i < 8; i++) { S += rs[i]; S2 += rs2[i]; }
        float mu = S * (1.f / 1024.f);
        s_mu = mu;
        s_rstd = rsqrtf(S2 * (1.f / 1024.f) - mu * mu + 1e-5f);
    }
    __syncthreads();
    float mu = s_mu, rstd = s_rstd;
#pragma unroll
    for (int i = 0; i < 4; i++) {
        int idx = tid + i * 256;
        float x = (sh[idx] - mu) * rstd * lng[idx] + lnb[idx];
        sh[idx] = fmaxf(x, 0.f);
    }
    __syncthreads();
    if (w < 6) {
        float acc = 0.f;
        for (int i = lane; i < 1024; i += 32) acc = fmaf(sh[i], wout[w * 1024 + i], acc);
        for (int o = 16; o; o >>= 1) acc += __shfl_down_sync(0xffffffffu, acc, o);
        if (!lane) g_em[(size_t)row * 6 + w] = acc + bout[w];
    }
}

// ---- K5: CRF numerator + forward algorithm + mean. One block, warp/batch. --
// NOTE: attention_mask arrives as int32 (harness promotes bool -> int32).
__global__ void crf_k(const int* __restrict__ tags, const int* __restrict__ mask,
                      const float* __restrict__ st, const float* __restrict__ en,
                      const float* __restrict__ tr, float* __restrict__ out) {
    __shared__ float ll[32];
    const unsigned full = 0xffffffffu;
    const int b = threadIdx.x >> 5, j = threadIdx.x & 31;
    const bool act = j < 6;
    float trc[6];
#pragma unroll
    for (int i = 0; i < 6; i++) trc[i] = tr[i * 6 + (act ? j : 0)];
    float alpha = act ? (st[j] + g_em[b * 6 + j]) : -1e30f;
    int prev = tags[b * TT];
    float score = st[prev] + g_em[b * 6 + prev];
    int cnt = (mask[b * TT] != 0) ? 1 : 0;
    for (int t = 1; t < TT; t++) {
        float m = (mask[b * TT + t] != 0) ? 1.f : 0.f;
        cnt += (int)m;
        int tg = tags[b * TT + t];
        const float* emt = g_em + ((size_t)t * BB + b) * 6;
        score += m * (tr[prev * 6 + tg] + emt[tg]);
        prev = tg;
        float av[6];
#pragma unroll
        for (int i = 0; i < 6; i++) av[i] = __shfl_sync(full, alpha, i);
        if (act) {
            float mx = -1e30f;
#pragma unroll
            for (int i = 0; i < 6; i++) mx = fmaxf(mx, av[i] + trc[i]);
            float sm = 0.f;
#pragma unroll
            for (int i = 0; i < 6; i++) sm += expf(av[i] + trc[i] - mx);
            float nxt = mx + logf(sm) + emt[j];
            if (m > 0.f) alpha = nxt;
        }
    }
    int ltag = tags[b * TT + (cnt - 1)];
    float num = score + en[ltag];
    float v = act ? (alpha + en[j]) : -1e30f;
    float mx = v;
    for (int o = 16; o; o >>= 1) mx = fmaxf(mx, __shfl_xor_sync(full, mx, o));
    float sm = act ? expf(v - mx) : 0.f;
    for (int o = 16; o; o >>= 1) sm += __shfl_xor_sync(full, sm, o);
    float den = mx + logf(sm);
    if (j == 0) ll[b] = num - den;
    __syncthreads();
    if (threadIdx.x == 0) {
        float s = 0.f;
        for (int i = 0; i < 32; i++) s += ll[i];
        *out = -s * (1.f / 32.f);
    }
}

extern "C" void kernel_launch(void* const* d_in, const int* in_sizes, int n_in,
                              void* d_out, int out_size) {
    const int*   ids  = (const int*)  d_in[0];
    const float* eeg  = (const float*)d_in[1];
    const int*   tags = (const int*)  d_in[2];
    const int*   mask = (const int*)  d_in[3];
    const float* emb  = (const float*)d_in[4];
    const float* wihf = (const float*)d_in[5];
    const float* whhf = (const float*)d_in[6];
    const float* bf   = (const float*)d_in[7];
    const float* wihb = (const float*)d_in[8];
    const float* whhb = (const float*)d_in[9];
    const float* bb   = (const float*)d_in[10];
    const float* lng  = (const float*)d_in[11];
    const float* lnb  = (const float*)d_in[12];
    const float* wout = (const float*)d_in[13];
    const float* bout = (const float*)d_in[14];
    const float* st   = (const float*)d_in[15];
    const float* en   = (const float*)d_in[16];
    const float* tr   = (const float*)d_in[17];
    float* out = (float*)d_out;

    static int smem_set = 0;
    if (!smem_set) {
        cudaFuncSetAttribute(lstm_rec_k, cudaFuncAttributeMaxDynamicSharedMemorySize, 170000);
        smem_set = 1;
    }
    build_x_k<<<NROWS, 128>>>(ids, eeg, emb);
    pack_w_k<<<NG, 128>>>(wihf, wihb, bf, bb);
    gemm_pre_k<<<dim3(64, 256), 256>>>();
    lstm_rec_k<<<128, 256, 168192>>>(whhf, whhb);
    ln_emit_k<<<NROWS, 256>>>(lng, lnb, wout, bout);
    crf_k<<<1, 1024>>>(tags, mask, st, en, tr, out);
}

// round 4
// speedup vs baseline: 2.5029x; 2.5029x over previous
#include <cuda_runtime.h>
#include <cuda_bf16.h>
#include <math.h>

#define TT 512
#define BB 32
#define HH 512
#define NROWS 16384
#define LDK 544            // 514 padded to /16
#define NG 4096

__device__ __nv_bfloat16 g_xb[(size_t)NROWS * LDK];
__device__ __nv_bfloat16 g_wb[(size_t)NG * LDK];
__device__ float         g_bias[NG];
__device__ float         g_pre[(size_t)NROWS * NG];
__device__ __nv_bfloat16 g_hs[(size_t)2 * TT * BB * HH];   // [dir][t][b][j]
__device__ float         g_em[(size_t)NROWS * 6];
__device__ int           g_bars[4];

static __device__ __forceinline__ unsigned packbf(float lo, float hi) {
    __nv_bfloat162 v = __floats2bfloat162_rn(lo, hi);
    return *reinterpret_cast<unsigned*>(&v);
}

static __device__ __forceinline__ void mma_bf16(float& c0, float& c1, float& c2, float& c3,
                                                unsigned a0, unsigned a1, unsigned a2, unsigned a3,
                                                unsigned b0, unsigned b1) {
    asm volatile(
        "mma.sync.aligned.m16n8k16.row.col.f32.bf16.bf16.f32 "
        "{%0,%1,%2,%3},{%4,%5,%6,%7},{%8,%9},{%0,%1,%2,%3};"
        : "+f"(c0), "+f"(c1), "+f"(c2), "+f"(c3)
        : "r"(a0), "r"(a1), "r"(a2), "r"(a3), "r"(b0), "r"(b1));
}

// ---- K1: x = [emb[ids] | eeg[:,:,4:6] | pad] -> bf16 [t*32+b][544] ---------
__global__ void build_x_k(const int* __restrict__ ids, const float* __restrict__ eeg,
                          const float* __restrict__ emb) {
    int row = blockIdx.x, t = row >> 5, b = row & 31;
    int id = ids[b * TT + t];
    const float* er = emb + (size_t)id * 512;
    __nv_bfloat16* xr = g_xb + (size_t)row * LDK;
    for (int d = threadIdx.x; d < LDK; d += blockDim.x) {
        float v;
        if (d < 512)      v = er[d];
        else if (d < 514) v = eeg[((size_t)(b * TT + t)) * 8 + 4 + (d - 512)];
        else              v = 0.f;
        xr[d] = __float2bfloat16(v);
    }
}

// ---- K1b: pack W_ih both dirs -> bf16 [4096][544], bias f32, reset bars ----
__global__ void pack_w_k(const float* __restrict__ wf, const float* __restrict__ wb,
                         const float* __restrict__ bf, const float* __restrict__ bbv) {
    int r = blockIdx.x;
    if (r == 0 && threadIdx.x < 4) g_bars[threadIdx.x] = 0;
    const float* src = (r < 2048) ? (wf + (size_t)r * 514) : (wb + (size_t)(r - 2048) * 514);
    __nv_bfloat16* dst = g_wb + (size_t)r * LDK;
    for (int d = threadIdx.x; d < LDK; d += blockDim.x)
        dst[d] = __float2bfloat16((d < 514) ? src[d] : 0.f);
    if (threadIdx.x == 0) g_bias[r] = (r < 2048) ? bf[r] : bbv[r - 2048];
}

// ---- K2: pre = x @ W^T + bias via bf16 mma. CTA 128x128, 8 warps 64x32 -----
__global__ void __launch_bounds__(256) gemm_pre_k() {
    __shared__ __align__(16) unsigned char As[128 * 48];
    __shared__ __align__(16) unsigned char Bs[128 * 48];
    const int tid = threadIdx.x;
    const int bn = blockIdx.x * 128, bm = blockIdx.y * 128;
    const int w = tid >> 5, l = tid & 31;
    const int wm = (w & 1) * 64, wn = (w >> 1) * 32;
    float acc[4][4][4];
#pragma unroll
    for (int i = 0; i < 4; i++)
#pragma unroll
        for (int j = 0; j < 4; j++)
#pragma unroll
            for (int k = 0; k < 4; k++) acc[i][j][k] = 0.f;

    const int lr = tid >> 1, lh = (tid & 1) * 16;   // loader: row, 16B half
    const char* Aptr = (const char*)(g_xb + (size_t)(bm + lr) * LDK);
    const char* Bptr = (const char*)(g_wb + (size_t)(bn + lr) * LDK);
    uint4 av = *(const uint4*)(Aptr + lh);
    uint4 bv = *(const uint4*)(Bptr + lh);

    for (int kt = 0; kt < 34; kt++) {
        *(uint4*)(As + lr * 48 + lh) = av;
        *(uint4*)(Bs + lr * 48 + lh) = bv;
        __syncthreads();
        if (kt < 33) {
            av = *(const uint4*)(Aptr + (kt + 1) * 32 + lh);
            bv = *(const uint4*)(Bptr + (kt + 1) * 32 + lh);
        }
        unsigned af[4][4], bfr[4][2];
#pragma unroll
        for (int mt = 0; mt < 4; mt++) {
            const unsigned char* p = As + (wm + mt * 16 + (l >> 2)) * 48 + ((l & 3) << 2);
            af[mt][0] = *(const unsigned*)(p);
            af[mt][1] = *(const unsigned*)(p + 8 * 48);
            af[mt][2] = *(const unsigned*)(p + 16);
            af[mt][3] = *(const unsigned*)(p + 8 * 48 + 16);
        }
#pragma unroll
        for (int nf = 0; nf < 4; nf++) {
            const unsigned char* p = Bs + (wn + nf * 8 + (l >> 2)) * 48 + ((l & 3) << 2);
            bfr[nf][0] = *(const unsigned*)(p);
            bfr[nf][1] = *(const unsigned*)(p + 16);
        }
#pragma unroll
        for (int mt = 0; mt < 4; mt++)
#pragma unroll
            for (int nf = 0; nf < 4; nf++)
                mma_bf16(acc[mt][nf][0], acc[mt][nf][1], acc[mt][nf][2], acc[mt][nf][3],
                         af[mt][0], af[mt][1], af[mt][2], af[mt][3],
                         bfr[nf][0], bfr[nf][1]);
        __syncthreads();
    }
#pragma unroll
    for (int mt = 0; mt < 4; mt++) {
        int m0 = bm + wm + mt * 16 + (l >> 2);
#pragma unroll
        for (int nf = 0; nf < 4; nf++) {
            int n0 = bn + wn + nf * 8 + ((l & 3) << 1);
            float2 bv2 = *(const float2*)&g_bias[n0];
            float2 o0 = make_float2(acc[mt][nf][0] + bv2.x, acc[mt][nf][1] + bv2.y);
            float2 o1 = make_float2(acc[mt][nf][2] + bv2.x, acc[mt][nf][3] + bv2.y);
            *(float2*)(g_pre + (size_t)m0 * NG + n0)       = o0;
            *(float2*)(g_pre + (size_t)(m0 + 8) * NG + n0) = o1;
        }
    }
}

// ---- K3: persistent BiLSTM, W_hh in register MMA fragments -----------------
// 64 CTAs = dir(2) x gate-chunk(32: 16 h-dims x 4 gates = 64 W rows).
__global__ void __launch_bounds__(256, 1) lstm_mma_k(const float* __restrict__ whhf,
                                                     const float* __restrict__ whhb) {
    __shared__ __align__(16) unsigned char Ab[32 * 1040];   // h tile, padded rows
    __shared__ float gsm[64][33];
    const int tid = threadIdx.x, cta = blockIdx.x;
    const int dir = cta >> 5, g = cta & 31;
    const int w = tid >> 5, l = tid & 31;

    // B fragments: warp owns rows w*8..w*8+7 of the 64-row chunk, all K=512.
    const int nloc = w * 8 + (l >> 2);
    const int Gn = nloc >> 4, jn = nloc & 15;
    const float* Wrow = (dir ? whhb : whhf) + (size_t)(Gn * 512 + g * 16 + jn) * 512;
    unsigned Bf0[32], Bf1[32];
#pragma unroll
    for (int ks = 0; ks < 32; ks++) {
        const float* p = Wrow + ks * 16 + ((l & 3) << 1);
        Bf0[ks] = packbf(p[0], p[1]);
        Bf1[ks] = packbf(p[8], p[9]);
    }
    // gate-combine mapping: thread -> (jj, b0g) and (jj, b0g+16)
    const int jj = tid & 15, b0g = tid >> 4;
    float cs0 = 0.f, cs1 = 0.f;

    for (int step = 0; step < TT; step++) {
        const int t = dir ? (TT - 1 - step) : step;
        // prefetch pre-activations for this t (independent of barrier)
        const float* pp = g_pre + ((size_t)t * BB) * NG + dir * 2048 + g * 16 + jj;
        float pg[2][4];
#pragma unroll
        for (int pi = 0; pi < 2; pi++) {
            int b = b0g + pi * 16;
#pragma unroll
            for (int Gi = 0; Gi < 4; Gi++)
                pg[pi][Gi] = __ldg(pp + (size_t)b * NG + Gi * 512);
        }
        float acc[2][4] = {{0.f,0.f,0.f,0.f},{0.f,0.f,0.f,0.f}};
        if (step > 0) {
            const int tp = dir ? (t + 1) : (t - 1);
            if (tid == 0) {
                const int target = 32 * step;
                while (atomicAdd(&g_bars[dir], 0) < target) __nanosleep(32);
            }
            __syncthreads();
            const uint4* src = (const uint4*)(g_hs + (((size_t)dir * TT + tp) * BB) * HH);
            for (int i = tid; i < 2048; i += 256)
                *(uint4*)(Ab + (i >> 6) * 1040 + (i & 63) * 16) = __ldcg(src + i);
            __syncthreads();
#pragma unroll
            for (int ks = 0; ks < 32; ks++) {
#pragma unroll
                for (int mt = 0; mt < 2; mt++) {
                    const unsigned char* p = Ab + (mt * 16 + (l >> 2)) * 1040 + ks * 32 + ((l & 3) << 2);
                    unsigned a0 = *(const unsigned*)p;
                    unsigned a1 = *(const unsigned*)(p + 8 * 1040);
                    unsigned a2 = *(const unsigned*)(p + 16);
                    unsigned a3 = *(const unsigned*)(p + 8 * 1040 + 16);
                    mma_bf16(acc[mt][0], acc[mt][1], acc[mt][2], acc[mt][3],
                             a0, a1, a2, a3, Bf0[ks], Bf1[ks]);
                }
            }
        }
        // scatter C frags: C[m=batch][n=gate-row]
        {
            const int rr = w * 8 + ((l & 3) << 1);
            const int bb_ = l >> 2;
#pragma unroll
            for (int mt = 0; mt < 2; mt++) {
                gsm[rr    ][mt * 16 + bb_    ] = acc[mt][0];
                gsm[rr + 1][mt * 16 + bb_    ] = acc[mt][1];
                gsm[rr    ][mt * 16 + bb_ + 8] = acc[mt][2];
                gsm[rr + 1][mt * 16 + bb_ + 8] = acc[mt][3];
            }
        }
        __syncthreads();
        // combine gates, update c/h, store h bf16
        __nv_bfloat16* hdst = g_hs + (((size_t)dir * TT + t) * BB) * HH + g * 16 + jj;
#pragma unroll
        for (int pi = 0; pi < 2; pi++) {
            int b = b0g + pi * 16;
            float gi = gsm[jj     ][b] + pg[pi][0];
            float gf = gsm[16 + jj][b] + pg[pi][1];
            float gg = gsm[32 + jj][b] + pg[pi][2];
            float go = gsm[48 + jj][b] + pg[pi][3];
            float si = 1.f / (1.f + expf(-gi));
            float sf = 1.f / (1.f + expf(-gf));
            float so = 1.f / (1.f + expf(-go));
            float& cs = pi ? cs1 : cs0;
            cs = sf * cs + si * tanhf(gg);
            float h = so * tanhf(cs);
            hdst[(size_t)b * HH] = __float2bfloat16(h);
        }
        __threadfence();
        __syncthreads();
        if (tid == 0) atomicAdd(&g_bars[dir], 1);
    }
}

// ---- K4: LayerNorm(1024) + ReLU + emission (K=6), h is bf16 ----------------
__global__ void __launch_bounds__(256) ln_emit_k(const float* __restrict__ lng,
                                                 const float* __restrict__ lnb,
                                                 const float* __restrict__ wout,
                                                 const float* __restrict__ bout) {
    __shared__ float sh[1024];
    __shared__ float rs[8], rs2[8];
    __shared__ float s_mu, s_rstd;
    const int row = blockIdx.x, tid = threadIdx.x;
    const int lane = tid & 31, w = tid >> 5;
    const __nv_bfloat16* hf = g_hs + (size_t)row * HH;
    const __nv_bfloat16* hb = g_hs + (size_t)TT * BB * HH + (size_t)row * HH;
    float s = 0.f, s2 = 0.f;
#pragma unroll
    for (int i = 0; i < 4; i++) {
        int idx = tid + i * 256;
        float x = (idx < 512) ? __bfloat162float(hf[idx]) : __bfloat162float(hb[idx - 512]);
        sh[idx] = x; s += x; s2 += x * x;
    }
    for (int o = 16; o; o >>= 1) {
        s  += __shfl_down_sync(0xffffffffu, s, o);
        s2 += __shfl_down_sync(0xffffffffu, s2, o);
    }
    if (!lane) { rs[w] = s; rs2[w] = s2; }
    __syncthreads();
    if (!tid) {
        float S = 0.f, S2 = 0.f;
        for (int i = 0; i < 8; i++) { S += rs[i]; S2 += rs2[i]; }
        float mu = S * (1.f / 1024.f);
        s_mu = mu;
        s_rstd = rsqrtf(S2 * (1.f / 1024.f) - mu * mu + 1e-5f);
    }
    __syncthreads();
    float mu = s_mu, rstd = s_rstd;
#pragma unroll
    for (int i = 0; i < 4; i++) {
        int idx = tid + i * 256;
        float x = (sh[idx] - mu) * rstd * lng[idx] + lnb[idx];
        sh[idx] = fmaxf(x, 0.f);
    }
    __syncthreads();
    if (w < 6) {
        float acc = 0.f;
        for (int i = lane; i < 1024; i += 32) acc = fmaf(sh[i], wout[w * 1024 + i], acc);
        for (int o = 16; o; o >>= 1) acc += __shfl_down_sync(0xffffffffu, acc, o);
        if (!lane) g_em[(size_t)row * 6 + w] = acc + bout[w];
    }
}

// ---- K5: CRF (numerator + forward algorithm + mean). mask is int32. --------
__global__ void crf_k(const int* __restrict__ tags, const int* __restrict__ mask,
                      const float* __restrict__ st, const float* __restrict__ en,
                      const float* __restrict__ tr, float* __restrict__ out) {
    __shared__ float ll[32];
    const unsigned full = 0xffffffffu;
    const int b = threadIdx.x >> 5, j = threadIdx.x & 31;
    const bool act = j < 6;
    float trc[6];
#pragma unroll
    for (int i = 0; i < 6; i++) trc[i] = tr[i * 6 + (act ? j : 0)];
    float alpha = act ? (st[j] + g_em[b * 6 + j]) : -1e30f;
    int prev = tags[b * TT];
    float score = st[prev] + g_em[b * 6 + prev];
    int cnt = (mask[b * TT] != 0) ? 1 : 0;
    for (int t = 1; t < TT; t++) {
        float m = (mask[b * TT + t] != 0) ? 1.f : 0.f;
        cnt += (int)m;
        int tg = tags[b * TT + t];
        const float* emt = g_em + ((size_t)t * BB + b) * 6;
        score += m * (tr[prev * 6 + tg] + emt[tg]);
        prev = tg;
        float av[6];
#pragma unroll
        for (int i = 0; i < 6; i++) av[i] = __shfl_sync(full, alpha, i);
        if (act) {
            float mx = -1e30f;
#pragma unroll
            for (int i = 0; i < 6; i++) mx = fmaxf(mx, av[i] + trc[i]);
            float sm = 0.f;
#pragma unroll
            for (int i = 0; i < 6; i++) sm += expf(av[i] + trc[i] - mx);
            float nxt = mx + logf(sm) + emt[j];
            if (m > 0.f) alpha = nxt;
        }
    }
    int ltag = tags[b * TT + (cnt - 1)];
    float num = score + en[ltag];
    float v = act ? (alpha + en[j]) : -1e30f;
    float mx = v;
    for (int o = 16; o; o >>= 1) mx = fmaxf(mx, __shfl_xor_sync(full, mx, o));
    float sm = act ? expf(v - mx) : 0.f;
    for (int o = 16; o; o >>= 1) sm += __shfl_xor_sync(full, sm, o);
    float den = mx + logf(sm);
    if (j == 0) ll[b] = num - den;
    __syncthreads();
    if (threadIdx.x == 0) {
        float s = 0.f;
        for (int i = 0; i < 32; i++) s += ll[i];
        *out = -s * (1.f / 32.f);
    }
}

extern "C" void kernel_launch(void* const* d_in, const int* in_sizes, int n_in,
                              void* d_out, int out_size) {
    const int*   ids  = (const int*)  d_in[0];
    const float* eeg  = (const float*)d_in[1];
    const int*   tags = (const int*)  d_in[2];
    const int*   mask = (const int*)  d_in[3];
    const float* emb  = (const float*)d_in[4];
    const float* wihf = (const float*)d_in[5];
    const float* whhf = (const float*)d_in[6];
    const float* bf   = (const float*)d_in[7];
    const float* wihb = (const float*)d_in[8];
    const float* whhb = (const float*)d_in[9];
    const float* bb   = (const float*)d_in[10];
    const float* lng  = (const float*)d_in[11];
    const float* lnb  = (const float*)d_in[12];
    const float* wout = (const float*)d_in[13];
    const float* bout = (const float*)d_in[14];
    const float* st   = (const float*)d_in[15];
    const float* en   = (const float*)d_in[16];
    const float* tr   = (const float*)d_in[17];
    float* out = (float*)d_out;

    build_x_k<<<NROWS, 128>>>(ids, eeg, emb);
    pack_w_k<<<NG, 128>>>(wihf, wihb, bf, bb);
    gemm_pre_k<<<dim3(32, 128), 256>>>();
    lstm_mma_k<<<64, 256>>>(whhf, whhb);
    ln_emit_k<<<NROWS, 256>>>(lng, lnb, wout, bout);
    crf_k<<<1, 1024>>>(tags, mask, st, en, tr, out);
}

// round 5
// speedup vs baseline: 2.5849x; 1.0328x over previous
#include <cuda_runtime.h>
#include <cuda_bf16.h>
#include <math.h>

#define TT 512
#define BB 32
#define HH 512
#define NROWS 16384
#define LDK 544            // 514 padded to /16
#define NG 4096

__device__ __nv_bfloat16 g_xb[(size_t)NROWS * LDK];
__device__ __nv_bfloat16 g_wb[(size_t)NG * LDK];
__device__ float         g_bias[NG];
__device__ float         g_pre[(size_t)NROWS * NG];
__device__ __nv_bfloat16 g_hs[(size_t)2 * TT * BB * HH];   // [dir][t][b][j]
__device__ float         g_em[(size_t)NROWS * 6];
__device__ int           g_bars[4];

static __device__ __forceinline__ unsigned packbf(float lo, float hi) {
    __nv_bfloat162 v = __floats2bfloat162_rn(lo, hi);
    return *reinterpret_cast<unsigned*>(&v);
}

static __device__ __forceinline__ void mma_bf16(float& c0, float& c1, float& c2, float& c3,
                                                unsigned a0, unsigned a1, unsigned a2, unsigned a3,
                                                unsigned b0, unsigned b1) {
    asm volatile(
        "mma.sync.aligned.m16n8k16.row.col.f32.bf16.bf16.f32 "
        "{%0,%1,%2,%3},{%4,%5,%6,%7},{%8,%9},{%0,%1,%2,%3};"
        : "+f"(c0), "+f"(c1), "+f"(c2), "+f"(c3)
        : "r"(a0), "r"(a1), "r"(a2), "r"(a3), "r"(b0), "r"(b1));
}

// ---- K1: x = [emb[ids] | eeg[:,:,4:6] | pad] -> bf16 [t*32+b][544] ---------
__global__ void build_x_k(const int* __restrict__ ids, const float* __restrict__ eeg,
                          const float* __restrict__ emb) {
    int row = blockIdx.x, t = row >> 5, b = row & 31;
    int id = ids[b * TT + t];
    const float* er = emb + (size_t)id * 512;
    __nv_bfloat16* xr = g_xb + (size_t)row * LDK;
    for (int d = threadIdx.x; d < LDK; d += blockDim.x) {
        float v;
        if (d < 512)      v = er[d];
        else if (d < 514) v = eeg[((size_t)(b * TT + t)) * 8 + 4 + (d - 512)];
        else              v = 0.f;
        xr[d] = __float2bfloat16(v);
    }
}

// ---- K1b: pack W_ih both dirs -> bf16 [4096][544], bias f32, reset bars ----
__global__ void pack_w_k(const float* __restrict__ wf, const float* __restrict__ wb,
                         const float* __restrict__ bf, const float* __restrict__ bbv) {
    int r = blockIdx.x;
    if (r == 0 && threadIdx.x < 4) g_bars[threadIdx.x] = 0;
    const float* src = (r < 2048) ? (wf + (size_t)r * 514) : (wb + (size_t)(r - 2048) * 514);
    __nv_bfloat16* dst = g_wb + (size_t)r * LDK;
    for (int d = threadIdx.x; d < LDK; d += blockDim.x)
        dst[d] = __float2bfloat16((d < 514) ? src[d] : 0.f);
    if (threadIdx.x == 0) g_bias[r] = (r < 2048) ? bf[r] : bbv[r - 2048];
}

// ---- K2: pre = x @ W^T + bias via bf16 mma. CTA 128x128, 8 warps 64x32 -----
__global__ void __launch_bounds__(256) gemm_pre_k() {
    __shared__ __align__(16) unsigned char As[128 * 48];
    __shared__ __align__(16) unsigned char Bs[128 * 48];
    const int tid = threadIdx.x;
    const int bn = blockIdx.x * 128, bm = blockIdx.y * 128;
    const int w = tid >> 5, l = tid & 31;
    const int wm = (w & 1) * 64, wn = (w >> 1) * 32;
    float acc[4][4][4];
#pragma unroll
    for (int i = 0; i < 4; i++)
#pragma unroll
        for (int j = 0; j < 4; j++)
#pragma unroll
            for (int k = 0; k < 4; k++) acc[i][j][k] = 0.f;

    const int lr = tid >> 1, lh = (tid & 1) * 16;
    const char* Aptr = (const char*)(g_xb + (size_t)(bm + lr) * LDK);
    const char* Bptr = (const char*)(g_wb + (size_t)(bn + lr) * LDK);
    uint4 av = *(const uint4*)(Aptr + lh);
    uint4 bv = *(const uint4*)(Bptr + lh);

    for (int kt = 0; kt < 34; kt++) {
        *(uint4*)(As + lr * 48 + lh) = av;
        *(uint4*)(Bs + lr * 48 + lh) = bv;
        __syncthreads();
        if (kt < 33) {
            av = *(const uint4*)(Aptr + (kt + 1) * 32 + lh);
            bv = *(const uint4*)(Bptr + (kt + 1) * 32 + lh);
        }
        unsigned af[4][4], bfr[4][2];
#pragma unroll
        for (int mt = 0; mt < 4; mt++) {
            const unsigned char* p = As + (wm + mt * 16 + (l >> 2)) * 48 + ((l & 3) << 2);
            af[mt][0] = *(const unsigned*)(p);
            af[mt][1] = *(const unsigned*)(p + 8 * 48);
            af[mt][2] = *(const unsigned*)(p + 16);
            af[mt][3] = *(const unsigned*)(p + 8 * 48 + 16);
        }
#pragma unroll
        for (int nf = 0; nf < 4; nf++) {
            const unsigned char* p = Bs + (wn + nf * 8 + (l >> 2)) * 48 + ((l & 3) << 2);
            bfr[nf][0] = *(const unsigned*)(p);
            bfr[nf][1] = *(const unsigned*)(p + 16);
        }
#pragma unroll
        for (int mt = 0; mt < 4; mt++)
#pragma unroll
            for (int nf = 0; nf < 4; nf++)
                mma_bf16(acc[mt][nf][0], acc[mt][nf][1], acc[mt][nf][2], acc[mt][nf][3],
                         af[mt][0], af[mt][1], af[mt][2], af[mt][3],
                         bfr[nf][0], bfr[nf][1]);
        __syncthreads();
    }
#pragma unroll
    for (int mt = 0; mt < 4; mt++) {
        int m0 = bm + wm + mt * 16 + (l >> 2);
#pragma unroll
        for (int nf = 0; nf < 4; nf++) {
            int n0 = bn + wn + nf * 8 + ((l & 3) << 1);
            float2 bv2 = *(const float2*)&g_bias[n0];
            float2 o0 = make_float2(acc[mt][nf][0] + bv2.x, acc[mt][nf][1] + bv2.y);
            float2 o1 = make_float2(acc[mt][nf][2] + bv2.x, acc[mt][nf][3] + bv2.y);
            *(float2*)(g_pre + (size_t)m0 * NG + n0)       = o0;
            *(float2*)(g_pre + (size_t)(m0 + 8) * NG + n0) = o1;
        }
    }
}

// ---- K3: persistent BiLSTM, W_hh in register MMA fragments -----------------
// 64 CTAs = dir(2) x gate-chunk(32). Release/acquire counter sync (no RMW poll,
// no threadfence): producer bar.sync + red.release; consumer ld.acquire spin.
__global__ void __launch_bounds__(256, 1) lstm_mma_k(const float* __restrict__ whhf,
                                                     const float* __restrict__ whhb) {
    __shared__ __align__(16) unsigned char Ab[32 * 1040];
    __shared__ float gsm[64][33];
    const int tid = threadIdx.x, cta = blockIdx.x;
    const int dir = cta >> 5, g = cta & 31;
    const int w = tid >> 5, l = tid & 31;
    int* ctr = &g_bars[dir];

    const int nloc = w * 8 + (l >> 2);
    const int Gn = nloc >> 4, jn = nloc & 15;
    const float* Wrow = (dir ? whhb : whhf) + (size_t)(Gn * 512 + g * 16 + jn) * 512;
    unsigned Bf0[32], Bf1[32];
#pragma unroll
    for (int ks = 0; ks < 32; ks++) {
        const float* p = Wrow + ks * 16 + ((l & 3) << 1);
        Bf0[ks] = packbf(p[0], p[1]);
        Bf1[ks] = packbf(p[8], p[9]);
    }
    const int jj = tid & 15, b0g = tid >> 4;
    float cs0 = 0.f, cs1 = 0.f;

    for (int step = 0; step < TT; step++) {
        const int t = dir ? (TT - 1 - step) : step;
        const float* pp = g_pre + ((size_t)t * BB) * NG + dir * 2048 + g * 16 + jj;
        float pg[2][4];
#pragma unroll
        for (int pi = 0; pi < 2; pi++) {
            int b = b0g + pi * 16;
#pragma unroll
            for (int Gi = 0; Gi < 4; Gi++)
                pg[pi][Gi] = __ldg(pp + (size_t)b * NG + Gi * 512);
        }
        float acc[2][4] = {{0.f,0.f,0.f,0.f},{0.f,0.f,0.f,0.f}};
        if (step > 0) {
            const int tp = dir ? (t + 1) : (t - 1);
            if (tid == 0) {
                const int target = 32 * step;
                int v;
                do {
                    asm volatile("ld.acquire.gpu.global.b32 %0, [%1];"
                                 : "=r"(v) : "l"(ctr) : "memory");
                } while (v < target);
            }
            __syncthreads();
            const uint4* src = (const uint4*)(g_hs + (((size_t)dir * TT + tp) * BB) * HH);
            for (int i = tid; i < 2048; i += 256)
                *(uint4*)(Ab + (i >> 6) * 1040 + (i & 63) * 16) = __ldcg(src + i);
            __syncthreads();
#pragma unroll
            for (int ks = 0; ks < 32; ks++) {
#pragma unroll
                for (int mt = 0; mt < 2; mt++) {
                    const unsigned char* p = Ab + (mt * 16 + (l >> 2)) * 1040 + ks * 32 + ((l & 3) << 2);
                    unsigned a0 = *(const unsigned*)p;
                    unsigned a1 = *(const unsigned*)(p + 8 * 1040);
                    unsigned a2 = *(const unsigned*)(p + 16);
                    unsigned a3 = *(const unsigned*)(p + 8 * 1040 + 16);
                    mma_bf16(acc[mt][0], acc[mt][1], acc[mt][2], acc[mt][3],
                             a0, a1, a2, a3, Bf0[ks], Bf1[ks]);
                }
            }
        }
        {
            const int rr = w * 8 + ((l & 3) << 1);
            const int bb_ = l >> 2;
#pragma unroll
            for (int mt = 0; mt < 2; mt++) {
                gsm[rr    ][mt * 16 + bb_    ] = acc[mt][0];
                gsm[rr + 1][mt * 16 + bb_    ] = acc[mt][1];
                gsm[rr    ][mt * 16 + bb_ + 8] = acc[mt][2];
                gsm[rr + 1][mt * 16 + bb_ + 8] = acc[mt][3];
            }
        }
        __syncthreads();
        __nv_bfloat16* hdst = g_hs + (((size_t)dir * TT + t) * BB) * HH + g * 16 + jj;
#pragma unroll
        for (int pi = 0; pi < 2; pi++) {
            int b = b0g + pi * 16;
            float gi = gsm[jj     ][b] + pg[pi][0];
            float gf = gsm[16 + jj][b] + pg[pi][1];
            float gg = gsm[32 + jj][b] + pg[pi][2];
            float go = gsm[48 + jj][b] + pg[pi][3];
            float si = 1.f / (1.f + expf(-gi));
            float sf = 1.f / (1.f + expf(-gf));
            float so = 1.f / (1.f + expf(-go));
            float& cs = pi ? cs1 : cs0;
            cs = sf * cs + si * tanhf(gg);
            float h = so * tanhf(cs);
            hdst[(size_t)b * HH] = __float2bfloat16(h);
        }
        __syncthreads();   // all h-stores issued before thread0's release
        if (tid == 0)
            asm volatile("red.release.gpu.global.add.s32 [%0], 1;" :: "l"(ctr) : "memory");
    }
}

// ---- K4: LayerNorm(1024) + ReLU + emission (K=6), h is bf16 ----------------
__global__ void __launch_bounds__(256) ln_emit_k(const float* __restrict__ lng,
                                                 const float* __restrict__ lnb,
                                                 const float* __restrict__ wout,
                                                 const float* __restrict__ bout) {
    __shared__ float sh[1024];
    __shared__ float rs[8], rs2[8];
    __shared__ float s_mu, s_rstd;
    const int row = blockIdx.x, tid = threadIdx.x;
    const int lane = tid & 31, w = tid >> 5;
    const __nv_bfloat16* hf = g_hs + (size_t)row * HH;
    const __nv_bfloat16* hb = g_hs + (size_t)TT * BB * HH + (size_t)row * HH;
    float s = 0.f, s2 = 0.f;
#pragma unroll
    for (int i = 0; i < 4; i++) {
        int idx = tid + i * 256;
        float x = (idx < 512) ? __bfloat162float(hf[idx]) : __bfloat162float(hb[idx - 512]);
        sh[idx] = x; s += x; s2 += x * x;
    }
    for (int o = 16; o; o >>= 1) {
        s  += __shfl_down_sync(0xffffffffu, s, o);
        s2 += __shfl_down_sync(0xffffffffu, s2, o);
    }
    if (!lane) { rs[w] = s; rs2[w] = s2; }
    __syncthreads();
    if (!tid) {
        float S = 0.f, S2 = 0.f;
        for (int i = 0; i < 8; i++) { S += rs[i]; S2 += rs2[i]; }
        float mu = S * (1.f / 1024.f);
        s_mu = mu;
        s_rstd = rsqrtf(S2 * (1.f / 1024.f) - mu * mu + 1e-5f);
    }
    __syncthreads();
    float mu = s_mu, rstd = s_rstd;
#pragma unroll
    for (int i = 0; i < 4; i++) {
        int idx = tid + i * 256;
        float x = (sh[idx] - mu) * rstd * lng[idx] + lnb[idx];
        sh[idx] = fmaxf(x, 0.f);
    }
    __syncthreads();
    if (w < 6) {
        float acc = 0.f;
        for (int i = lane; i < 1024; i += 32) acc = fmaf(sh[i], wout[w * 1024 + i], acc);
        for (int o = 16; o; o >>= 1) acc += __shfl_down_sync(0xffffffffu, acc, o);
        if (!lane) g_em[(size_t)row * 6 + w] = acc + bout[w];
    }
}

// ---- K5: CRF (numerator + forward algorithm + mean). mask is int32. --------
__global__ void crf_k(const int* __restrict__ tags, const int* __restrict__ mask,
                      const float* __restrict__ st, const float* __restrict__ en,
                      const float* __restrict__ tr, float* __restrict__ out) {
    __shared__ float ll[32];
    const unsigned full = 0xffffffffu;
    const int b = threadIdx.x >> 5, j = threadIdx.x & 31;
    const bool act = j < 6;
    float trc[6];
#pragma unroll
    for (int i = 0; i < 6; i++) trc[i] = tr[i * 6 + (act ? j : 0)];
    float alpha = act ? (st[j] + g_em[b * 6 + j]) : -1e30f;
    int prev = tags[b * TT];
    float score = st[prev] + g_em[b * 6 + prev];
    int cnt = (mask[b * TT] != 0) ? 1 : 0;
    for (int t = 1; t < TT; t++) {
        float m = (mask[b * TT + t] != 0) ? 1.f : 0.f;
        cnt += (int)m;
        int tg = tags[b * TT + t];
        const float* emt = g_em + ((size_t)t * BB + b) * 6;
        score += m * (tr[prev * 6 + tg] + emt[tg]);
        prev = tg;
        float av[6];
#pragma unroll
        for (int i = 0; i < 6; i++) av[i] = __shfl_sync(full, alpha, i);
        if (act) {
            float mx = -1e30f;
#pragma unroll
            for (int i = 0; i < 6; i++) mx = fmaxf(mx, av[i] + trc[i]);
            float sm = 0.f;
#pragma unroll
            for (int i = 0; i < 6; i++) sm += expf(av[i] + trc[i] - mx);
            float nxt = mx + logf(sm) + emt[j];
            if (m > 0.f) alpha = nxt;
        }
    }
    int ltag = tags[b * TT + (cnt - 1)];
    float num = score + en[ltag];
    float v = act ? (alpha + en[j]) : -1e30f;
    float mx = v;
    for (int o = 16; o; o >>= 1) mx = fmaxf(mx, __shfl_xor_sync(full, mx, o));
    float sm = act ? expf(v - mx) : 0.f;
    for (int o = 16; o; o >>= 1) sm += __shfl_xor_sync(full, sm, o);
    float den = mx + logf(sm);
    if (j == 0) ll[b] = num - den;
    __syncthreads();
    if (threadIdx.x == 0) {
        float s = 0.f;
        for (int i = 0; i < 32; i++) s += ll[i];
        *out = -s * (1.f / 32.f);
    }
}

extern "C" void kernel_launch(void* const* d_in, const int* in_sizes, int n_in,
                              void* d_out, int out_size) {
    const int*   ids  = (const int*)  d_in[0];
    const float* eeg  = (const float*)d_in[1];
    const int*   tags = (const int*)  d_in[2];
    const int*   mask = (const int*)  d_in[3];
    const float* emb  = (const float*)d_in[4];
    const float* wihf = (const float*)d_in[5];
    const float* whhf = (const float*)d_in[6];
    const float* bf   = (const float*)d_in[7];
    const float* wihb = (const float*)d_in[8];
    const float* whhb = (const float*)d_in[9];
    const float* bb   = (const float*)d_in[10];
    const float* lng  = (const float*)d_in[11];
    const float* lnb  = (const float*)d_in[12];
    const float* wout = (const float*)d_in[13];
    const float* bout = (const float*)d_in[14];
    const float* st   = (const float*)d_in[15];
    const float* en   = (const float*)d_in[16];
    const float* tr   = (const float*)d_in[17];
    float* out = (float*)d_out;

    build_x_k<<<NROWS, 128>>>(ids, eeg, emb);
    pack_w_k<<<NG, 128>>>(wihf, wihb, bf, bb);
    gemm_pre_k<<<dim3(32, 128), 256>>>();
    lstm_mma_k<<<64, 256>>>(whhf, whhb);
    ln_emit_k<<<NROWS, 256>>>(lng, lnb, wout, bout);
    crf_k<<<1, 1024>>>(tags, mask, st, en, tr, out);
}

// round 6
// speedup vs baseline: 2.6289x; 1.0170x over previous
#include <cuda_runtime.h>
#include <cuda_bf16.h>
#include <math.h>

#define TT 512
#define BB 32
#define HH 512
#define NROWS 16384
#define LDK 544            // 514 padded to /16
#define NG 4096

__device__ __nv_bfloat16 g_xb[(size_t)NROWS * LDK];
__device__ __nv_bfloat16 g_wb[(size_t)NG * LDK];
__device__ float         g_bias[NG];
__device__ float         g_pre[(size_t)NROWS * NG];
// h layout: [dir][t][g(32)][b(32)][16]  (chunk-major, 1KB contiguous per CTA)
__device__ __nv_bfloat16 g_hs[(size_t)2 * TT * BB * HH];
__device__ float         g_em[(size_t)NROWS * 6];
__device__ int           g_bars[4];

static __device__ __forceinline__ unsigned packbf(float lo, float hi) {
    __nv_bfloat162 v = __floats2bfloat162_rn(lo, hi);
    return *reinterpret_cast<unsigned*>(&v);
}

static __device__ __forceinline__ void mma_bf16(float& c0, float& c1, float& c2, float& c3,
                                                unsigned a0, unsigned a1, unsigned a2, unsigned a3,
                                                unsigned b0, unsigned b1) {
    asm volatile(
        "mma.sync.aligned.m16n8k16.row.col.f32.bf16.bf16.f32 "
        "{%0,%1,%2,%3},{%4,%5,%6,%7},{%8,%9},{%0,%1,%2,%3};"
        : "+f"(c0), "+f"(c1), "+f"(c2), "+f"(c3)
        : "r"(a0), "r"(a1), "r"(a2), "r"(a3), "r"(b0), "r"(b1));
}

static __device__ __forceinline__ float fsig(float x) {
    return __frcp_rn(1.f + __expf(-x));
}
static __device__ __forceinline__ float ftanh(float x) {
    float t = __expf(2.f * x);
    return (t - 1.f) * __frcp_rn(t + 1.f);
}

// ---- K1: x = [emb[ids] | eeg[:,:,4:6] | pad] -> bf16 [t*32+b][544] ---------
__global__ void build_x_k(const int* __restrict__ ids, const float* __restrict__ eeg,
                          const float* __restrict__ emb) {
    int row = blockIdx.x, t = row >> 5, b = row & 31;
    int id = ids[b * TT + t];
    const float* er = emb + (size_t)id * 512;
    __nv_bfloat16* xr = g_xb + (size_t)row * LDK;
    for (int d = threadIdx.x; d < LDK; d += blockDim.x) {
        float v;
        if (d < 512)      v = er[d];
        else if (d < 514) v = eeg[((size_t)(b * TT + t)) * 8 + 4 + (d - 512)];
        else              v = 0.f;
        xr[d] = __float2bfloat16(v);
    }
}

// ---- K1b: pack W_ih both dirs -> bf16 [4096][544], bias f32, reset bars ----
__global__ void pack_w_k(const float* __restrict__ wf, const float* __restrict__ wb,
                         const float* __restrict__ bf, const float* __restrict__ bbv) {
    int r = blockIdx.x;
    if (r == 0 && threadIdx.x < 4) g_bars[threadIdx.x] = 0;
    const float* src = (r < 2048) ? (wf + (size_t)r * 514) : (wb + (size_t)(r - 2048) * 514);
    __nv_bfloat16* dst = g_wb + (size_t)r * LDK;
    for (int d = threadIdx.x; d < LDK; d += blockDim.x)
        dst[d] = __float2bfloat16((d < 514) ? src[d] : 0.f);
    if (threadIdx.x == 0) g_bias[r] = (r < 2048) ? bf[r] : bbv[r - 2048];
}

// ---- K2: pre = x @ W^T + bias via bf16 mma. CTA 128x128, 8 warps 64x32 -----
__global__ void __launch_bounds__(256) gemm_pre_k() {
    __shared__ __align__(16) unsigned char As[128 * 48];
    __shared__ __align__(16) unsigned char Bs[128 * 48];
    const int tid = threadIdx.x;
    const int bn = blockIdx.x * 128, bm = blockIdx.y * 128;
    const int w = tid >> 5, l = tid & 31;
    const int wm = (w & 1) * 64, wn = (w >> 1) * 32;
    float acc[4][4][4];
#pragma unroll
    for (int i = 0; i < 4; i++)
#pragma unroll
        for (int j = 0; j < 4; j++)
#pragma unroll
            for (int k = 0; k < 4; k++) acc[i][j][k] = 0.f;

    const int lr = tid >> 1, lh = (tid & 1) * 16;
    const char* Aptr = (const char*)(g_xb + (size_t)(bm + lr) * LDK);
    const char* Bptr = (const char*)(g_wb + (size_t)(bn + lr) * LDK);
    uint4 av = *(const uint4*)(Aptr + lh);
    uint4 bv = *(const uint4*)(Bptr + lh);

    for (int kt = 0; kt < 34; kt++) {
        *(uint4*)(As + lr * 48 + lh) = av;
        *(uint4*)(Bs + lr * 48 + lh) = bv;
        __syncthreads();
        if (kt < 33) {
            av = *(const uint4*)(Aptr + (kt + 1) * 32 + lh);
            bv = *(const uint4*)(Bptr + (kt + 1) * 32 + lh);
        }
        unsigned af[4][4], bfr[4][2];
#pragma unroll
        for (int mt = 0; mt < 4; mt++) {
            const unsigned char* p = As + (wm + mt * 16 + (l >> 2)) * 48 + ((l & 3) << 2);
            af[mt][0] = *(const unsigned*)(p);
            af[mt][1] = *(const unsigned*)(p + 8 * 48);
            af[mt][2] = *(const unsigned*)(p + 16);
            af[mt][3] = *(const unsigned*)(p + 8 * 48 + 16);
        }
#pragma unroll
        for (int nf = 0; nf < 4; nf++) {
            const unsigned char* p = Bs + (wn + nf * 8 + (l >> 2)) * 48 + ((l & 3) << 2);
            bfr[nf][0] = *(const unsigned*)(p);
            bfr[nf][1] = *(const unsigned*)(p + 16);
        }
#pragma unroll
        for (int mt = 0; mt < 4; mt++)
#pragma unroll
            for (int nf = 0; nf < 4; nf++)
                mma_bf16(acc[mt][nf][0], acc[mt][nf][1], acc[mt][nf][2], acc[mt][nf][3],
                         af[mt][0], af[mt][1], af[mt][2], af[mt][3],
                         bfr[nf][0], bfr[nf][1]);
        __syncthreads();
    }
#pragma unroll
    for (int mt = 0; mt < 4; mt++) {
        int m0 = bm + wm + mt * 16 + (l >> 2);
#pragma unroll
        for (int nf = 0; nf < 4; nf++) {
            int n0 = bn + wn + nf * 8 + ((l & 3) << 1);
            float2 bv2 = *(const float2*)&g_bias[n0];
            float2 o0 = make_float2(acc[mt][nf][0] + bv2.x, acc[mt][nf][1] + bv2.y);
            float2 o1 = make_float2(acc[mt][nf][2] + bv2.x, acc[mt][nf][3] + bv2.y);
            *(float2*)(g_pre + (size_t)m0 * NG + n0)       = o0;
            *(float2*)(g_pre + (size_t)(m0 + 8) * NG + n0) = o1;
        }
    }
}

// ---- K3: persistent BiLSTM, W_hh in register MMA frags, ldmatrix A ---------
__global__ void __launch_bounds__(256, 1) lstm_mma_k(const float* __restrict__ whhf,
                                                     const float* __restrict__ whhb) {
    __shared__ __align__(16) unsigned char Ab[32 * 1040];
    __shared__ float gsm[64][33];
    const int tid = threadIdx.x, cta = blockIdx.x;
    const int dir = cta >> 5, g = cta & 31;
    const int w = tid >> 5, l = tid & 31;
    int* ctr = &g_bars[dir];

    const int nloc = w * 8 + (l >> 2);
    const int Gn = nloc >> 4, jn = nloc & 15;
    const float* Wrow = (dir ? whhb : whhf) + (size_t)(Gn * 512 + g * 16 + jn) * 512;
    unsigned Bf0[32], Bf1[32];
#pragma unroll
    for (int ks = 0; ks < 32; ks++) {
        const float* p = Wrow + ks * 16 + ((l & 3) << 1);
        Bf0[ks] = packbf(p[0], p[1]);
        Bf1[ks] = packbf(p[8], p[9]);
    }
    const int jj = tid & 15, b0g = tid >> 4;
    float cs0 = 0.f, cs1 = 0.f;

    // ldmatrix lane address components (row = l&15, k-half = l>>4)
    const unsigned ab_base = (unsigned)__cvta_generic_to_shared(Ab);
    const unsigned lm_off = (unsigned)((l & 15) * 1040 + (l >> 4) * 16);

    for (int step = 0; step < TT; step++) {
        const int t = dir ? (TT - 1 - step) : step;
        const float* pp = g_pre + ((size_t)t * BB) * NG + dir * 2048 + g * 16 + jj;
        float pg[2][4];
#pragma unroll
        for (int pi = 0; pi < 2; pi++) {
            int b = b0g + pi * 16;
#pragma unroll
            for (int Gi = 0; Gi < 4; Gi++)
                pg[pi][Gi] = __ldg(pp + (size_t)b * NG + Gi * 512);
        }
        float acc[2][4] = {{0.f,0.f,0.f,0.f},{0.f,0.f,0.f,0.f}};
        if (step > 0) {
            const int tp = dir ? (t + 1) : (t - 1);
            // per-warp acquire poll (uniform across lanes; broadcast load)
            {
                const int target = 32 * step;
                int v;
                do {
                    asm volatile("ld.acquire.gpu.global.b32 %0, [%1];"
                                 : "=r"(v) : "l"(ctr) : "memory");
                } while (v < target);
            }
            // stage h[tp]: [g(32)][b(32)][16] -> Ab[b][g*16..]
            const uint4* src = (const uint4*)(g_hs + ((size_t)dir * TT + tp) * 16384);
            for (int i = tid; i < 2048; i += 256) {
                int cr = i >> 1, half = i & 1;
                int bsrc = cr & 31, gg = cr >> 5;
                *(uint4*)(Ab + bsrc * 1040 + gg * 32 + half * 16) = __ldcg(src + i);
            }
            __syncthreads();
#pragma unroll
            for (int ks = 0; ks < 32; ks++) {
#pragma unroll
                for (int mt = 0; mt < 2; mt++) {
                    unsigned a0, a1, a2, a3;
                    unsigned addr = ab_base + (unsigned)(mt * 16 * 1040 + ks * 32) + lm_off;
                    asm volatile("ldmatrix.sync.aligned.m8n8.x4.shared.b16 {%0,%1,%2,%3},[%4];"
                                 : "=r"(a0), "=r"(a1), "=r"(a2), "=r"(a3) : "r"(addr));
                    mma_bf16(acc[mt][0], acc[mt][1], acc[mt][2], acc[mt][3],
                             a0, a1, a2, a3, Bf0[ks], Bf1[ks]);
                }
            }
        }
        {
            const int rr = w * 8 + ((l & 3) << 1);
            const int bb_ = l >> 2;
#pragma unroll
            for (int mt = 0; mt < 2; mt++) {
                gsm[rr    ][mt * 16 + bb_    ] = acc[mt][0];
                gsm[rr + 1][mt * 16 + bb_    ] = acc[mt][1];
                gsm[rr    ][mt * 16 + bb_ + 8] = acc[mt][2];
                gsm[rr + 1][mt * 16 + bb_ + 8] = acc[mt][3];
            }
        }
        __syncthreads();
        // combine gates; store h chunk contiguously: [g][b][16]
        __nv_bfloat16* hdst = g_hs + (((size_t)dir * TT + t) * 32 + g) * 512 + jj;
#pragma unroll
        for (int pi = 0; pi < 2; pi++) {
            int b = b0g + pi * 16;
            float gi = gsm[jj     ][b] + pg[pi][0];
            float gf = gsm[16 + jj][b] + pg[pi][1];
            float gg = gsm[32 + jj][b] + pg[pi][2];
            float go = gsm[48 + jj][b] + pg[pi][3];
            float si = fsig(gi), sf = fsig(gf), so = fsig(go);
            float& cs = pi ? cs1 : cs0;
            cs = sf * cs + si * ftanh(gg);
            float h = so * ftanh(cs);
            hdst[b * 16] = __float2bfloat16(h);
        }
        __syncthreads();   // all h-stores ordered before thread0's release
        if (tid == 0)
            asm volatile("red.release.gpu.global.add.s32 [%0], 1;" :: "l"(ctr) : "memory");
    }
}

// ---- K4: LayerNorm(1024) + ReLU + emission; h layout [dir][t][g][b][16] ----
__global__ void __launch_bounds__(256) ln_emit_k(const float* __restrict__ lng,
                                                 const float* __restrict__ lnb,
                                                 const float* __restrict__ wout,
                                                 const float* __restrict__ bout) {
    __shared__ float sh[1024];
    __shared__ float rs[8], rs2[8];
    __shared__ float s_mu, s_rstd;
    const int row = blockIdx.x, tid = threadIdx.x;
    const int lane = tid & 31, w = tid >> 5;
    const int t = row >> 5, b = row & 31;
    const __nv_bfloat16* hf = g_hs + ((size_t)t * 32) * 512 + b * 16;
    const __nv_bfloat16* hb = g_hs + ((size_t)TT + t) * 32 * 512 + b * 16;
    float s = 0.f, s2 = 0.f;
#pragma unroll
    for (int i = 0; i < 4; i++) {
        int idx = tid + i * 256;
        int d = idx & 511;
        int gg = d >> 4, jjv = d & 15;
        float x = (idx < 512) ? __bfloat162float(hf[gg * 512 + jjv])
                              : __bfloat162float(hb[gg * 512 + jjv]);
        sh[idx] = x; s += x; s2 += x * x;
    }
    for (int o = 16; o; o >>= 1) {
        s  += __shfl_down_sync(0xffffffffu, s, o);
        s2 += __shfl_down_sync(0xffffffffu, s2, o);
    }
    if (!lane) { rs[w] = s; rs2[w] = s2; }
    __syncthreads();
    if (!tid) {
        float S = 0.f, S2 = 0.f;
        for (int i = 0; i < 8; i++) { S += rs[i]; S2 += rs2[i]; }
        float mu = S * (1.f / 1024.f);
        s_mu = mu;
        s_rstd = rsqrtf(S2 * (1.f / 1024.f) - mu * mu + 1e-5f);
    }
    __syncthreads();
    float mu = s_mu, rstd = s_rstd;
#pragma unroll
    for (int i = 0; i < 4; i++) {
        int idx = tid + i * 256;
        float x = (sh[idx] - mu) * rstd * lng[idx] + lnb[idx];
        sh[idx] = fmaxf(x, 0.f);
    }
    __syncthreads();
    if (w < 6) {
        float acc = 0.f;
        for (int i = lane; i < 1024; i += 32) acc = fmaf(sh[i], wout[w * 1024 + i], acc);
        for (int o = 16; o; o >>= 1) acc += __shfl_down_sync(0xffffffffu, acc, o);
        if (!lane) g_em[(size_t)row * 6 + w] = acc + bout[w];
    }
}

// ---- K5: CRF (numerator + forward algorithm + mean). mask is int32. --------
__global__ void crf_k(const int* __restrict__ tags, const int* __restrict__ mask,
                      const float* __restrict__ st, const float* __restrict__ en,
                      const float* __restrict__ tr, float* __restrict__ out) {
    __shared__ float ll[32];
    const unsigned full = 0xffffffffu;
    const int b = threadIdx.x >> 5, j = threadIdx.x & 31;
    const bool act = j < 6;
    float trc[6];
#pragma unroll
    for (int i = 0; i < 6; i++) trc[i] = tr[i * 6 + (act ? j : 0)];
    float alpha = act ? (st[j] + g_em[b * 6 + j]) : -1e30f;
    int prev = tags[b * TT];
    float score = st[prev] + g_em[b * 6 + prev];
    int cnt = (mask[b * TT] != 0) ? 1 : 0;
    for (int t = 1; t < TT; t++) {
        float m = (mask[b * TT + t] != 0) ? 1.f : 0.f;
        cnt += (int)m;
        int tg = tags[b * TT + t];
        const float* emt = g_em + ((size_t)t * BB + b) * 6;
        score += m * (tr[prev * 6 + tg] + emt[tg]);
        prev = tg;
        float av[6];
#pragma unroll
        for (int i = 0; i < 6; i++) av[i] = __shfl_sync(full, alpha, i);
        if (act) {
            float mx = -1e30f;
#pragma unroll
            for (int i = 0; i < 6; i++) mx = fmaxf(mx, av[i] + trc[i]);
            float sm = 0.f;
#pragma unroll
            for (int i = 0; i < 6; i++) sm += expf(av[i] + trc[i] - mx);
            float nxt = mx + logf(sm) + emt[j];
            if (m > 0.f) alpha = nxt;
        }
    }
    int ltag = tags[b * TT + (cnt - 1)];
    float num = score + en[ltag];
    float v = act ? (alpha + en[j]) : -1e30f;
    float mx = v;
    for (int o = 16; o; o >>= 1) mx = fmaxf(mx, __shfl_xor_sync(full, mx, o));
    float sm = act ? expf(v - mx) : 0.f;
    for (int o = 16; o; o >>= 1) sm += __shfl_xor_sync(full, sm, o);
    float den = mx + logf(sm);
    if (j == 0) ll[b] = num - den;
    __syncthreads();
    if (threadIdx.x == 0) {
        float s = 0.f;
        for (int i = 0; i < 32; i++) s += ll[i];
        *out = -s * (1.f / 32.f);
    }
}

extern "C" void kernel_launch(void* const* d_in, const int* in_sizes, int n_in,
                              void* d_out, int out_size) {
    const int*   ids  = (const int*)  d_in[0];
    const float* eeg  = (const float*)d_in[1];
    const int*   tags = (const int*)  d_in[2];
    const int*   mask = (const int*)  d_in[3];
    const float* emb  = (const float*)d_in[4];
    const float* wihf = (const float*)d_in[5];
    const float* whhf = (const float*)d_in[6];
    const float* bf   = (const float*)d_in[7];
    const float* wihb = (const float*)d_in[8];
    const float* whhb = (const float*)d_in[9];
    const float* bb   = (const float*)d_in[10];
    const float* lng  = (const float*)d_in[11];
    const float* lnb  = (const float*)d_in[12];
    const float* wout = (const float*)d_in[13];
    const float* bout = (const float*)d_in[14];
    const float* st   = (const float*)d_in[15];
    const float* en   = (const float*)d_in[16];
    const float* tr   = (const float*)d_in[17];
    float* out = (float*)d_out;

    build_x_k<<<NROWS, 128>>>(ids, eeg, emb);
    pack_w_k<<<NG, 128>>>(wihf, wihb, bf, bb);
    gemm_pre_k<<<dim3(32, 128), 256>>>();
    lstm_mma_k<<<64, 256>>>(whhf, whhb);
    ln_emit_k<<<NROWS, 256>>>(lng, lnb, wout, bout);
    crf_k<<<1, 1024>>>(tags, mask, st, en, tr, out);
}